// round 16
// baseline (speedup 1.0000x reference)
#include <cuda_runtime.h>
#include <cuda_bf16.h>
#include <mma.h>
#include <cstdint>

#define NN 20000
#define EE 160000
#define E2 320000
#define HD 128

// ---------------- static scratch (no allocations allowed) ----------------
static __device__ float g_PQ[(size_t)NN * 256];  // cols 0-127 = P(dst proj), 128-255 = Q(src proj)
static __device__ float g_C[NN * HD];
static __device__ float g_H[NN * HD];
static __device__ float g_X[(size_t)NN * 512];   // [h | Lh | L^2h | L^3h]
static __device__ float g_degf[NN];
static __device__ float g_dis[NN];
static __device__ int   g_deg[NN];               // zero at every kernel_launch entry (invariant)
static __device__ int   g_cnt[NN];
static __device__ int   g_off[NN + 1];
static __device__ int2  g_csr[E2];               // {src, rid}

// ---------------- f32x2 helpers ----------------
__device__ __forceinline__ unsigned long long packf2(float lo, float hi) {
    unsigned long long r;
    asm("mov.b64 %0, {%1, %2};" : "=l"(r) : "f"(lo), "f"(hi));
    return r;
}
__device__ __forceinline__ float2 unpackf2(unsigned long long v) {
    float2 r;
    asm("mov.b64 {%0, %1}, %2;" : "=f"(r.x), "=f"(r.y) : "l"(v));
    return r;
}
__device__ __forceinline__ unsigned long long fmaf2(unsigned long long a, unsigned long long b,
                                                    unsigned long long c) {
    unsigned long long d;
    asm("fma.rn.f32x2 %0, %1, %2, %3;" : "=l"(d) : "l"(a), "l"(b), "l"(c));
    return d;
}

// ---------------- CSR: histogram (g_deg pre-zeroed by invariant) ----------------
__global__ void k_hist(const int* __restrict__ ei) {
    int e = blockIdx.x * blockDim.x + threadIdx.x;
    if (e >= EE) return;
    int s = ei[e], d = ei[EE + e];
    atomicAdd(&g_deg[d], 1);
    atomicAdd(&g_deg[s], 1);
}

// scan: offsets + degf/dis; zeroes g_cnt (for fill) and g_deg (restores invariant)
__global__ void k_scan() {
    __shared__ int part[1024];
    const int CH = (NN + 1023) / 1024;
    int t = threadIdx.x;
    int base = t * CH;
    int s = 0;
    for (int j = 0; j < CH; j++) {
        int idx = base + j;
        if (idx < NN) s += g_deg[idx];
    }
    part[t] = s;
    __syncthreads();
    for (int off = 1; off < 1024; off <<= 1) {
        int v = (t >= off) ? part[t - off] : 0;
        __syncthreads();
        part[t] += v;
        __syncthreads();
    }
    int run = (t > 0) ? part[t - 1] : 0;
    for (int j = 0; j < CH; j++) {
        int idx = base + j;
        if (idx < NN) {
            g_off[idx] = run;
            int d = g_deg[idx];
            run += d;
            g_cnt[idx] = 0;
            g_deg[idx] = 0;
            g_degf[idx] = (float)d;
            g_dis[idx]  = (d > 0) ? rsqrtf((float)d) : 0.0f;
        }
    }
    if (t == 1023) g_off[NN] = run;
}

// ---------------- fused CSR-fill + (mask MLP + EA0 projections) ----------------
#define FILL_BLOCKS 625
#define MASK_BLOCKS 2500
__global__ __launch_bounds__(256)
void k_fillmask(const int* __restrict__ ei,
                const float* __restrict__ mask, const float* __restrict__ x,
                const float* __restrict__ w1, const float* __restrict__ b1,
                const float* __restrict__ w2, const float* __restrict__ b2,
                const float* __restrict__ ea_w1, float* __restrict__ PQ) {
    if (blockIdx.x < FILL_BLOCKS) {
        int e = blockIdx.x * blockDim.x + threadIdx.x;
        if (e >= EE) return;
        int s0 = ei[e], d0 = ei[EE + e];
        int p = atomicAdd(&g_cnt[d0], 1);
        g_csr[g_off[d0] + p] = make_int2(s0, e);
        p = atomicAdd(&g_cnt[s0], 1);
        g_csr[g_off[s0] + p] = make_int2(d0, e);
        return;
    }
    __shared__ float sw1[16 * 128];
    __shared__ float sb1[128];
    __shared__ float sw2[128 * 16];
    __shared__ float sb2[16];
    __shared__ float swp[16 * 256];
    for (int v = threadIdx.x; v < 2048; v += blockDim.x) { sw1[v] = w1[v]; sw2[v] = w2[v]; }
    for (int v = threadIdx.x; v < 128; v += blockDim.x) sb1[v] = b1[v];
    if (threadIdx.x < 16) sb2[threadIdx.x] = b2[threadIdx.x];
    for (int v = threadIdx.x; v < 4096; v += blockDim.x) {
        int k = v >> 8, c = v & 255;
        swp[v] = (c < 128) ? ea_w1[k * 128 + c] : ea_w1[(16 + k) * 128 + (c - 128)];
    }
    __syncthreads();

    int gt = (blockIdx.x - FILL_BLOCKS) * blockDim.x + threadIdx.x;
    int i = gt >> 5;
    if (i >= NN) return;
    int lane = threadIdx.x & 31;
    int f = lane * 4;
    float m = (lane < 16) ? mask[(size_t)i * 16 + lane] : 0.0f;
    float xv = (lane < 16) ? x[(size_t)i * 16 + lane] : 0.0f;
    float4 h = *(const float4*)&sb1[f];
#pragma unroll
    for (int k = 0; k < 16; k++) {
        float a = __shfl_sync(0xffffffffu, m, k);
        const float4 w = *(const float4*)&sw1[k * 128 + f];
        h.x += a * w.x; h.y += a * w.y; h.z += a * w.z; h.w += a * w.w;
    }
    h.x = fmaxf(h.x, 0.f); h.y = fmaxf(h.y, 0.f);
    h.z = fmaxf(h.z, 0.f); h.w = fmaxf(h.w, 0.f);

    float o[16];
#pragma unroll
    for (int t = 0; t < 16; t++) o[t] = 0.0f;
    float hv[4] = {h.x, h.y, h.z, h.w};
#pragma unroll
    for (int j = 0; j < 4; j++) {
        const float* wrow = &sw2[(f + j) * 16];
        float hj = hv[j];
#pragma unroll
        for (int t = 0; t < 16; t++) o[t] += hj * wrow[t];
    }
#pragma unroll
    for (int off = 16; off > 0; off >>= 1)
#pragma unroll
        for (int t = 0; t < 16; t++) o[t] += __shfl_xor_sync(0xffffffffu, o[t], off);

    int f8 = lane * 8;
    float4 r0 = make_float4(0.f, 0.f, 0.f, 0.f);
    float4 r1 = make_float4(0.f, 0.f, 0.f, 0.f);
#pragma unroll
    for (int k = 0; k < 16; k++) {
        float hk = o[k] + sb2[k] + __shfl_sync(0xffffffffu, xv, k);
        const float4 wa = *(const float4*)&swp[k * 256 + f8];
        const float4 wb = *(const float4*)&swp[k * 256 + f8 + 4];
        r0.x += hk * wa.x; r0.y += hk * wa.y; r0.z += hk * wa.z; r0.w += hk * wa.w;
        r1.x += hk * wb.x; r1.y += hk * wb.y; r1.z += hk * wb.z; r1.w += hk * wb.w;
    }
    *(float4*)(PQ + (size_t)i * 256 + f8)     = r0;
    *(float4*)(PQ + (size_t)i * 256 + f8 + 4) = r1;
}

// ---------------- bf16x3 tensor-core GEMM, 8 warps ----------------
__device__ __forceinline__ void split4(float4 a, __nv_bfloat16* ph, __nv_bfloat16* pm) {
    __nv_bfloat162 h0 = __floats2bfloat162_rn(a.x, a.y);
    __nv_bfloat162 h1 = __floats2bfloat162_rn(a.z, a.w);
    __nv_bfloat162 m0 = __floats2bfloat162_rn(a.x - __bfloat162float(h0.x),
                                              a.y - __bfloat162float(h0.y));
    __nv_bfloat162 m1 = __floats2bfloat162_rn(a.z - __bfloat162float(h1.x),
                                              a.w - __bfloat162float(h1.y));
    *(__nv_bfloat162*)ph = h0; *(__nv_bfloat162*)(ph + 2) = h1;
    *(__nv_bfloat162*)pm = m0; *(__nv_bfloat162*)(pm + 2) = m1;
}

#define GEMM_SMEM 55296

__global__ __launch_bounds__(256)
void k_gemm_tc(const float* __restrict__ A, int lda,
               const float* __restrict__ B, long bStride,
               float* __restrict__ D, int ldd, long dStride,
               const float* __restrict__ bias, const float* __restrict__ rowscale,
               int M, int K, int N, int relu) {
    using namespace nvcuda;
    extern __shared__ char sm_raw[];
    __nv_bfloat16* Ah = (__nv_bfloat16*)sm_raw;
    __nv_bfloat16* Am = Ah + 2 * 2560;
    __nv_bfloat16* Bh = Am + 2 * 2560;
    __nv_bfloat16* Bm = Bh + 2 * 4352;

    B += (size_t)blockIdx.z * bStride;
    D += (size_t)blockIdx.z * dStride;

    int tid = threadIdx.x;
    int wid = tid >> 5, lane = tid & 31;
    int wm = wid >> 1, wn = wid & 1;
    int row0 = blockIdx.y * 64, col0 = blockIdx.x * 128;

    wmma::fragment<wmma::accumulator, 16, 16, 16, float> acc[4];
#pragma unroll
    for (int ni = 0; ni < 4; ni++) wmma::fill_fragment(acc[ni], 0.0f);

    int KT = (K + 31) >> 5;

    auto loadA = [&](int kt, int buf) {
        int k0 = kt << 5;
#pragma unroll
        for (int i = 0; i < 2; i++) {
            int v = tid + (i << 8);
            int r = v >> 3, c = (v & 7) << 2;
            int gr = row0 + r;
            float4 a = make_float4(0.f, 0.f, 0.f, 0.f);
            if (gr < M && k0 + c < K) a = *(const float4*)(A + (size_t)gr * lda + k0 + c);
            int idx = buf * 2560 + r * 40 + c;
            split4(a, &Ah[idx], &Am[idx]);
        }
    };
    auto loadB = [&](int kt, int buf) {
        int k0 = kt << 5;
#pragma unroll
        for (int i = 0; i < 4; i++) {
            int v = tid + (i << 8);
            int r = v >> 5, c = (v & 31) << 2;
            int gc = col0 + c;
            float4 b = make_float4(0.f, 0.f, 0.f, 0.f);
            if (gc < N && k0 + r < K) b = *(const float4*)(B + (size_t)(k0 + r) * N + gc);
            int idx = buf * 4352 + r * 136 + c;
            split4(b, &Bh[idx], &Bm[idx]);
        }
    };

    loadA(0, 0); loadB(0, 0);
    __syncthreads();
    for (int kt = 0; kt < KT; kt++) {
        int buf = kt & 1;
        if (kt + 1 < KT) { loadA(kt + 1, buf ^ 1); loadB(kt + 1, buf ^ 1); }
#pragma unroll
        for (int ks = 0; ks < 2; ks++) {
            wmma::fragment<wmma::matrix_a, 16, 16, 16, __nv_bfloat16, wmma::row_major> ah, am;
            wmma::fragment<wmma::matrix_b, 16, 16, 16, __nv_bfloat16, wmma::row_major> bh[4], bm[4];
            int aoff = buf * 2560 + (wm * 16) * 40 + ks * 16;
            wmma::load_matrix_sync(ah, &Ah[aoff], 40);
            wmma::load_matrix_sync(am, &Am[aoff], 40);
#pragma unroll
            for (int ni = 0; ni < 4; ni++) {
                int boff = buf * 4352 + (ks * 16) * 136 + wn * 64 + ni * 16;
                wmma::load_matrix_sync(bh[ni], &Bh[boff], 136);
                wmma::load_matrix_sync(bm[ni], &Bm[boff], 136);
            }
#pragma unroll
            for (int ni = 0; ni < 4; ni++) {
                wmma::mma_sync(acc[ni], am, bh[ni], acc[ni]);
                wmma::mma_sync(acc[ni], ah, bm[ni], acc[ni]);
                wmma::mma_sync(acc[ni], ah, bh[ni], acc[ni]);
            }
        }
        __syncthreads();
    }

    bool direct = (bias == nullptr) && (rowscale == nullptr) && (relu == 0);
    if (direct) {   // NN % 16 == 0: full tiles or fully out of range
        int m0 = row0 + wm * 16;
        if (m0 + 16 <= M) {
#pragma unroll
            for (int ni = 0; ni < 4; ni++) {
                int n0 = col0 + wn * 64 + ni * 16;
                if (n0 < N)
                    wmma::store_matrix_sync(D + (size_t)m0 * ldd + n0, acc[ni], ldd,
                                            wmma::mem_row_major);
            }
        }
        return;
    }

    float* epi = (float*)sm_raw + wid * 320;
#pragma unroll
    for (int ni = 0; ni < 4; ni++) {
        wmma::store_matrix_sync(epi, acc[ni], 20, wmma::mem_row_major);
        __syncwarp();
        int r = lane >> 1, cb = (lane & 1) * 8;
        int m = row0 + wm * 16 + r;
        int n0 = col0 + wn * 64 + ni * 16 + cb;
        if (m < M && n0 < N) {
            float rs = rowscale ? rowscale[m] : 1.0f;
            float4 v0 = *(float4*)&epi[r * 20 + cb];
            float4 v1 = *(float4*)&epi[r * 20 + cb + 4];
            if (bias) {
                float4 b0 = *(const float4*)(bias + n0);
                float4 b1 = *(const float4*)(bias + n0 + 4);
                v0.x += rs * b0.x; v0.y += rs * b0.y; v0.z += rs * b0.z; v0.w += rs * b0.w;
                v1.x += rs * b1.x; v1.y += rs * b1.y; v1.z += rs * b1.z; v1.w += rs * b1.w;
            }
            if (relu) {
                v0.x = fmaxf(v0.x, 0.f); v0.y = fmaxf(v0.y, 0.f);
                v0.z = fmaxf(v0.z, 0.f); v0.w = fmaxf(v0.w, 0.f);
                v1.x = fmaxf(v1.x, 0.f); v1.y = fmaxf(v1.y, 0.f);
                v1.z = fmaxf(v1.z, 0.f); v1.w = fmaxf(v1.w, 0.f);
            }
            *(float4*)(D + (size_t)m * ldd + n0)     = v0;
            *(float4*)(D + (size_t)m * ldd + n0 + 4) = v1;
        }
        __syncwarp();
    }
}

// ---------------- shared edge-accumulation body (1 warp/node, 4 feats/lane) ----------
// acc = sum_nb relu( PQ[i,0:128] + PQ[src,128:256] + ea[rid]@W1e + b1 )  [lane's 4 feats]
// 4 messages computed with INTERLEAVED fma chains (8-way ILP) to hide FMA latency.
__device__ __forceinline__ float4 edge_accum(const float* __restrict__ PQ,
                                             const float* __restrict__ EA,
                                             const unsigned long long (&wp0)[16],
                                             const unsigned long long (&wp1)[16],
                                             unsigned long long bb01, unsigned long long bb23,
                                             int i, int lane, int f) {
    float4 p = *(const float4*)(PQ + (size_t)i * 256 + f);
    float4 acc = make_float4(0.f, 0.f, 0.f, 0.f);
    int s = g_off[i], s1 = g_off[i + 1];
    int l16 = lane & 15;
    bool hi = lane >= 16;

    for (; s + 4 <= s1; s += 4) {
        int2 e0 = g_csr[s], e1 = g_csr[s + 1], e2 = g_csr[s + 2], e3 = g_csr[s + 3];
        float4 q0 = *(const float4*)(PQ + (size_t)e0.x * 256 + 128 + f);
        float4 q1 = *(const float4*)(PQ + (size_t)e1.x * 256 + 128 + f);
        float4 q2 = *(const float4*)(PQ + (size_t)e2.x * 256 + 128 + f);
        float4 q3 = *(const float4*)(PQ + (size_t)e3.x * 256 + 128 + f);
        // lanes 0-15 carry even edge's ea row, lanes 16-31 the odd edge's
        float ev01 = EA[(size_t)(hi ? e1.y : e0.y) * 16 + l16];
        float ev23 = EA[(size_t)(hi ? e3.y : e2.y) * 16 + l16];

        unsigned long long m0a = bb01, m0b = bb23;
        unsigned long long m1a = bb01, m1b = bb23;
        unsigned long long m2a = bb01, m2b = bb23;
        unsigned long long m3a = bb01, m3b = bb23;
#pragma unroll
        for (int k = 0; k < 16; k++) {
            float v0 = __shfl_sync(0xffffffffu, ev01, k);
            float v1 = __shfl_sync(0xffffffffu, ev01, 16 + k);
            float v2 = __shfl_sync(0xffffffffu, ev23, k);
            float v3 = __shfl_sync(0xffffffffu, ev23, 16 + k);
            unsigned long long a0 = packf2(v0, v0);
            unsigned long long a1 = packf2(v1, v1);
            unsigned long long a2 = packf2(v2, v2);
            unsigned long long a3 = packf2(v3, v3);
            m0a = fmaf2(a0, wp0[k], m0a); m0b = fmaf2(a0, wp1[k], m0b);
            m1a = fmaf2(a1, wp0[k], m1a); m1b = fmaf2(a1, wp1[k], m1b);
            m2a = fmaf2(a2, wp0[k], m2a); m2b = fmaf2(a2, wp1[k], m2b);
            m3a = fmaf2(a3, wp0[k], m3a); m3b = fmaf2(a3, wp1[k], m3b);
        }
        float2 rA, rB;
        rA = unpackf2(m0a); rB = unpackf2(m0b);
        acc.x += fmaxf(p.x + q0.x + rA.x, 0.f);
        acc.y += fmaxf(p.y + q0.y + rA.y, 0.f);
        acc.z += fmaxf(p.z + q0.z + rB.x, 0.f);
        acc.w += fmaxf(p.w + q0.w + rB.y, 0.f);
        rA = unpackf2(m1a); rB = unpackf2(m1b);
        acc.x += fmaxf(p.x + q1.x + rA.x, 0.f);
        acc.y += fmaxf(p.y + q1.y + rA.y, 0.f);
        acc.z += fmaxf(p.z + q1.z + rB.x, 0.f);
        acc.w += fmaxf(p.w + q1.w + rB.y, 0.f);
        rA = unpackf2(m2a); rB = unpackf2(m2b);
        acc.x += fmaxf(p.x + q2.x + rA.x, 0.f);
        acc.y += fmaxf(p.y + q2.y + rA.y, 0.f);
        acc.z += fmaxf(p.z + q2.z + rB.x, 0.f);
        acc.w += fmaxf(p.w + q2.w + rB.y, 0.f);
        rA = unpackf2(m3a); rB = unpackf2(m3b);
        acc.x += fmaxf(p.x + q3.x + rA.x, 0.f);
        acc.y += fmaxf(p.y + q3.y + rA.y, 0.f);
        acc.z += fmaxf(p.z + q3.z + rB.x, 0.f);
        acc.w += fmaxf(p.w + q3.w + rB.y, 0.f);
    }
    for (; s < s1; s++) {
        int2 e = g_csr[s];
        float ev = (lane < 16) ? EA[(size_t)e.y * 16 + lane] : 0.0f;
        float4 q = *(const float4*)(PQ + (size_t)e.x * 256 + 128 + f);
        unsigned long long r01 = bb01, r23 = bb23;
#pragma unroll
        for (int k = 0; k < 16; k++) {
            float a = __shfl_sync(0xffffffffu, ev, k);
            unsigned long long aa = packf2(a, a);
            r01 = fmaf2(aa, wp0[k], r01);
            r23 = fmaf2(aa, wp1[k], r23);
        }
        float2 rA = unpackf2(r01), rB = unpackf2(r23);
        acc.x += fmaxf(p.x + q.x + rA.x, 0.f);
        acc.y += fmaxf(p.y + q.y + rA.y, 0.f);
        acc.z += fmaxf(p.z + q.z + rB.x, 0.f);
        acc.w += fmaxf(p.w + q.w + rB.y, 0.f);
    }
    return acc;
}

// ---------------- EA edge pass -> C ----------------
__global__ __launch_bounds__(256, 2)
void k_edge_f(const float* __restrict__ PQ,
              const float* __restrict__ EA, const float* __restrict__ W1e,
              const float* __restrict__ b1, float* __restrict__ S) {
    __shared__ float sw[16 * 128];
    __shared__ float sb[128];
    for (int v = threadIdx.x; v < 2048; v += blockDim.x) sw[v] = W1e[v];
    for (int v = threadIdx.x; v < 128; v += blockDim.x) sb[v] = b1[v];
    __syncthreads();
    int lane = threadIdx.x & 31;
    int f = lane * 4;
    unsigned long long wp0[16], wp1[16];
#pragma unroll
    for (int k = 0; k < 16; k++) {
        float4 t = *(const float4*)&sw[k * 128 + f];
        wp0[k] = packf2(t.x, t.y);
        wp1[k] = packf2(t.z, t.w);
    }
    float4 bbv = *(const float4*)&sb[f];
    unsigned long long bb01 = packf2(bbv.x, bbv.y);
    unsigned long long bb23 = packf2(bbv.z, bbv.w);

    int i = (blockIdx.x * blockDim.x + threadIdx.x) >> 5;
    if (i >= NN) return;
    float4 acc = edge_accum(PQ, EA, wp0, wp1, bb01, bb23, i, lane, f);
    *(float4*)(S + (size_t)i * HD + f) = acc;
}

// ---------------- final EA edge pass fused with out = C@W2 + deg*b2 (N=16) ----------
__global__ __launch_bounds__(256, 2)
void k_edge_out(const float* __restrict__ PQ,
                const float* __restrict__ EA, const float* __restrict__ W1e,
                const float* __restrict__ b1, const float* __restrict__ W2,
                const float* __restrict__ b2, float* __restrict__ out) {
    __shared__ float sw[16 * 128];
    __shared__ float sb[128];
    __shared__ float sw2[128 * 16];
    __shared__ float sb2[16];
    for (int v = threadIdx.x; v < 2048; v += blockDim.x) { sw[v] = W1e[v]; sw2[v] = W2[v]; }
    for (int v = threadIdx.x; v < 128; v += blockDim.x) sb[v] = b1[v];
    if (threadIdx.x < 16) sb2[threadIdx.x] = b2[threadIdx.x];
    __syncthreads();
    int lane = threadIdx.x & 31;
    int f = lane * 4;
    unsigned long long wp0[16], wp1[16];
#pragma unroll
    for (int k = 0; k < 16; k++) {
        float4 t = *(const float4*)&sw[k * 128 + f];
        wp0[k] = packf2(t.x, t.y);
        wp1[k] = packf2(t.z, t.w);
    }
    float4 bbv = *(const float4*)&sb[f];
    unsigned long long bb01 = packf2(bbv.x, bbv.y);
    unsigned long long bb23 = packf2(bbv.z, bbv.w);

    int i = (blockIdx.x * blockDim.x + threadIdx.x) >> 5;
    if (i >= NN) return;
    float4 acc = edge_accum(PQ, EA, wp0, wp1, bb01, bb23, i, lane, f);

    // out[i] = C[i]@W2 + deg[i]*b2, C row distributed 4 feats/lane
    float o[16];
#pragma unroll
    for (int t = 0; t < 16; t++) o[t] = 0.0f;
    float cv[4] = {acc.x, acc.y, acc.z, acc.w};
#pragma unroll
    for (int j = 0; j < 4; j++) {
        const float* wr = &sw2[(f + j) * 16];
        float cj = cv[j];
#pragma unroll
        for (int t = 0; t < 16; t++) o[t] += cj * wr[t];
    }
#pragma unroll
    for (int off = 16; off > 0; off >>= 1)
#pragma unroll
        for (int t = 0; t < 16; t++) o[t] += __shfl_xor_sync(0xffffffffu, o[t], off);
    if (lane < 16)
        out[(size_t)i * 16 + lane] = o[lane] + g_degf[i] * sb2[lane];
}

// ---------------- TAG propagation (norm folded via dis), ld = 512, 4x batched ---------
__global__ __launch_bounds__(256)
void k_prop(const float* __restrict__ Xc, float* __restrict__ Xn) {
    int i = (blockIdx.x * blockDim.x + threadIdx.x) >> 5;
    if (i >= NN) return;
    int lane = threadIdx.x & 31;
    int f = lane * 4;
    float4 acc = make_float4(0.f, 0.f, 0.f, 0.f);
    int s = g_off[i], s1 = g_off[i + 1];

    for (; s + 4 <= s1; s += 4) {
        int src[4];
#pragma unroll
        for (int j = 0; j < 4; j++) src[j] = g_csr[s + j].x;
        float nm[4]; float4 h[4];
#pragma unroll
        for (int j = 0; j < 4; j++) {
            nm[j] = __ldg(&g_dis[src[j]]);
            h[j] = *(const float4*)(Xc + (size_t)src[j] * 512 + f);
        }
#pragma unroll
        for (int j = 0; j < 4; j++) {
            acc.x += nm[j] * h[j].x; acc.y += nm[j] * h[j].y;
            acc.z += nm[j] * h[j].z; acc.w += nm[j] * h[j].w;
        }
    }
    for (; s < s1; s++) {
        int src = g_csr[s].x;
        float nm = __ldg(&g_dis[src]);
        float4 h = *(const float4*)(Xc + (size_t)src * 512 + f);
        acc.x += nm * h.x; acc.y += nm * h.y;
        acc.z += nm * h.z; acc.w += nm * h.w;
    }
    float di = __ldg(&g_dis[i]);
    acc.x *= di; acc.y *= di; acc.z *= di; acc.w *= di;
    *(float4*)(Xn + (size_t)i * 512 + f) = acc;
}

// ---------------- host ----------------
static void gemm(const float* A, int lda, const float* B, long bStride,
                 float* D, int ldd, long dStride,
                 const float* bias, const float* rowscale,
                 int M, int K, int N, int relu, int batch) {
    dim3 grid((N + 127) / 128, (M + 63) / 64, batch);
    k_gemm_tc<<<grid, 256, GEMM_SMEM>>>(A, lda, B, bStride, D, ldd, dStride,
                                        bias, rowscale, M, K, N, relu);
}

extern "C" void kernel_launch(void* const* d_in, const int* in_sizes, int n_in,
                              void* d_out, int out_size) {
    const float* x         = (const float*)d_in[0];
    const float* mask      = (const float*)d_in[1];
    const float* edge_attr = (const float*)d_in[2];
    const int* edge_index;
    int base;
    if (in_sizes[3] == 2 * EE) {
        edge_index = (const int*)d_in[3];
        base = 4;
    } else {
        edge_index = (const int*)d_in[n_in - 1];
        base = 3;
    }
    const float* m_w1   = (const float*)d_in[base + 0];
    const float* m_b1   = (const float*)d_in[base + 1];
    const float* m_w2   = (const float*)d_in[base + 2];
    const float* m_b2   = (const float*)d_in[base + 3];
    const float* ea0_w1 = (const float*)d_in[base + 4];
    const float* ea0_b1 = (const float*)d_in[base + 5];
    const float* ea0_w2 = (const float*)d_in[base + 6];
    const float* ea0_b2 = (const float*)d_in[base + 7];
    const float* tag0_w = (const float*)d_in[base + 8];
    const float* tag0_b = (const float*)d_in[base + 9];
    const float* ea1_w1 = (const float*)d_in[base + 10];
    const float* ea1_b1 = (const float*)d_in[base + 11];
    const float* ea1_w2 = (const float*)d_in[base + 12];
    const float* ea1_b2 = (const float*)d_in[base + 13];
    const float* tag1_w = (const float*)d_in[base + 14];
    const float* tag1_b = (const float*)d_in[base + 15];
    const float* ea2_w1 = (const float*)d_in[base + 16];
    const float* ea2_b1 = (const float*)d_in[base + 17];
    const float* ea2_w2 = (const float*)d_in[base + 18];
    const float* ea2_b2 = (const float*)d_in[base + 19];

    float *pPQ, *pC, *pH, *pX, *pdegf;
    cudaGetSymbolAddress((void**)&pPQ, g_PQ);
    cudaGetSymbolAddress((void**)&pC, g_C);
    cudaGetSymbolAddress((void**)&pH, g_H);
    cudaGetSymbolAddress((void**)&pX, g_X);
    cudaGetSymbolAddress((void**)&pdegf, g_degf);

    static int smem_set = 0;
    if (!smem_set) {
        cudaFuncSetAttribute(k_gemm_tc, cudaFuncAttributeMaxDynamicSharedMemorySize, GEMM_SMEM);
        smem_set = 1;
    }

    const int EB = 2500;    // node-warp kernels: 20000 warps / 8 per block

    // preprocessing: g_deg is zero on entry (invariant restored by k_scan)
    k_hist<<<(EE + 255) / 256, 256>>>(edge_index);
    k_scan<<<1, 1024>>>();
    k_fillmask<<<FILL_BLOCKS + MASK_BLOCKS, 256>>>(edge_index, mask, x,
                m_w1, m_b1, m_w2, m_b2, ea0_w1, pPQ);

    // ---- EA0 ----
    k_edge_f<<<EB, 256>>>(pPQ, edge_attr, ea0_w1 + 32 * 128, ea0_b1, pC);  // slot 3 <- ncu
    gemm(pC, 128, ea0_w2, 0, pX, 512, 0, ea0_b2, pdegf, NN, 128, 128, 1, 1);

    // ---- TAG0 ----
    k_prop<<<EB, 256>>>(pX,       pX + 128);
    k_prop<<<EB, 256>>>(pX + 128, pX + 256);
    k_prop<<<EB, 256>>>(pX + 256, pX + 384);
    gemm(pX, 512, tag0_w, 0, pH, 128, 0, tag0_b, nullptr, NN, 512, 128, 1, 1);

    // ---- EA1 ----
    gemm(pH, 128, ea1_w1, 128 * 128, pPQ, 256, 128, nullptr, nullptr, NN, 128, 128, 0, 2);
    k_edge_f<<<EB, 256>>>(pPQ, edge_attr, ea1_w1 + 256 * 128, ea1_b1, pC);
    gemm(pC, 128, ea1_w2, 0, pX, 512, 0, ea1_b2, pdegf, NN, 128, 128, 1, 1);

    // ---- TAG1 ----
    k_prop<<<EB, 256>>>(pX,       pX + 128);
    k_prop<<<EB, 256>>>(pX + 128, pX + 256);
    k_prop<<<EB, 256>>>(pX + 256, pX + 384);
    gemm(pX, 512, tag1_w, 0, pH, 128, 0, tag1_b, nullptr, NN, 512, 128, 1, 1);

    // ---- EA2 (edge pass fused with output projection) ----
    gemm(pH, 128, ea2_w1, 128 * 128, pPQ, 256, 128, nullptr, nullptr, NN, 128, 128, 0, 2);
    k_edge_out<<<EB, 256>>>(pPQ, edge_attr, ea2_w1 + 256 * 128, ea2_b1,
                            ea2_w2, ea2_b2, (float*)d_out);
}

// round 17
// speedup vs baseline: 1.0221x; 1.0221x over previous
#include <cuda_runtime.h>
#include <cuda_bf16.h>
#include <mma.h>
#include <cstdint>

#define NN 20000
#define EE 160000
#define E2 320000
#define HD 128

// ---------------- static scratch (no allocations allowed) ----------------
static __device__ float g_PQ[(size_t)NN * 256];  // cols 0-127 = P(dst proj), 128-255 = Q(src proj)
static __device__ float g_C[NN * HD];
static __device__ float g_H[NN * HD];
static __device__ float g_X[(size_t)NN * 512];   // [h | Lh | L^2h | L^3h]
static __device__ float g_degf[NN];
static __device__ float g_dis[NN];
static __device__ int   g_deg[NN];               // zero at every kernel_launch entry (invariant)
static __device__ int   g_cnt[NN];
static __device__ int   g_off[NN + 1];
static __device__ int2  g_csr[E2];               // {src, rid}

// ---------------- f32x2 helpers ----------------
__device__ __forceinline__ unsigned long long packf2(float lo, float hi) {
    unsigned long long r;
    asm("mov.b64 %0, {%1, %2};" : "=l"(r) : "f"(lo), "f"(hi));
    return r;
}
__device__ __forceinline__ float2 unpackf2(unsigned long long v) {
    float2 r;
    asm("mov.b64 {%0, %1}, %2;" : "=f"(r.x), "=f"(r.y) : "l"(v));
    return r;
}
__device__ __forceinline__ unsigned long long fmaf2(unsigned long long a, unsigned long long b,
                                                    unsigned long long c) {
    unsigned long long d;
    asm("fma.rn.f32x2 %0, %1, %2, %3;" : "=l"(d) : "l"(a), "l"(b), "l"(c));
    return d;
}

// ---------------- CSR: histogram (g_deg pre-zeroed by invariant) ----------------
__global__ void k_hist(const int* __restrict__ ei) {
    int e = blockIdx.x * blockDim.x + threadIdx.x;
    if (e >= EE) return;
    int s = ei[e], d = ei[EE + e];
    atomicAdd(&g_deg[d], 1);
    atomicAdd(&g_deg[s], 1);
}

// scan: offsets + degf/dis; zeroes g_cnt (for fill) and g_deg (restores invariant)
__global__ void k_scan() {
    __shared__ int part[1024];
    const int CH = (NN + 1023) / 1024;
    int t = threadIdx.x;
    int base = t * CH;
    int s = 0;
    for (int j = 0; j < CH; j++) {
        int idx = base + j;
        if (idx < NN) s += g_deg[idx];
    }
    part[t] = s;
    __syncthreads();
    for (int off = 1; off < 1024; off <<= 1) {
        int v = (t >= off) ? part[t - off] : 0;
        __syncthreads();
        part[t] += v;
        __syncthreads();
    }
    int run = (t > 0) ? part[t - 1] : 0;
    for (int j = 0; j < CH; j++) {
        int idx = base + j;
        if (idx < NN) {
            g_off[idx] = run;
            int d = g_deg[idx];
            run += d;
            g_cnt[idx] = 0;
            g_deg[idx] = 0;
            g_degf[idx] = (float)d;
            g_dis[idx]  = (d > 0) ? rsqrtf((float)d) : 0.0f;
        }
    }
    if (t == 1023) g_off[NN] = run;
}

// ---------------- fused CSR-fill + (mask MLP + EA0 projections) ----------------
#define FILL_BLOCKS 625
#define MASK_BLOCKS 2500
__global__ __launch_bounds__(256)
void k_fillmask(const int* __restrict__ ei,
                const float* __restrict__ mask, const float* __restrict__ x,
                const float* __restrict__ w1, const float* __restrict__ b1,
                const float* __restrict__ w2, const float* __restrict__ b2,
                const float* __restrict__ ea_w1, float* __restrict__ PQ) {
    if (blockIdx.x < FILL_BLOCKS) {
        int e = blockIdx.x * blockDim.x + threadIdx.x;
        if (e >= EE) return;
        int s0 = ei[e], d0 = ei[EE + e];
        int p = atomicAdd(&g_cnt[d0], 1);
        g_csr[g_off[d0] + p] = make_int2(s0, e);
        p = atomicAdd(&g_cnt[s0], 1);
        g_csr[g_off[s0] + p] = make_int2(d0, e);
        return;
    }
    __shared__ float sw1[16 * 128];
    __shared__ float sb1[128];
    __shared__ float sw2[128 * 16];
    __shared__ float sb2[16];
    __shared__ float swp[16 * 256];
    for (int v = threadIdx.x; v < 2048; v += blockDim.x) { sw1[v] = w1[v]; sw2[v] = w2[v]; }
    for (int v = threadIdx.x; v < 128; v += blockDim.x) sb1[v] = b1[v];
    if (threadIdx.x < 16) sb2[threadIdx.x] = b2[threadIdx.x];
    for (int v = threadIdx.x; v < 4096; v += blockDim.x) {
        int k = v >> 8, c = v & 255;
        swp[v] = (c < 128) ? ea_w1[k * 128 + c] : ea_w1[(16 + k) * 128 + (c - 128)];
    }
    __syncthreads();

    int gt = (blockIdx.x - FILL_BLOCKS) * blockDim.x + threadIdx.x;
    int i = gt >> 5;
    if (i >= NN) return;
    int lane = threadIdx.x & 31;
    int f = lane * 4;
    float m = (lane < 16) ? mask[(size_t)i * 16 + lane] : 0.0f;
    float xv = (lane < 16) ? x[(size_t)i * 16 + lane] : 0.0f;
    float4 h = *(const float4*)&sb1[f];
#pragma unroll
    for (int k = 0; k < 16; k++) {
        float a = __shfl_sync(0xffffffffu, m, k);
        const float4 w = *(const float4*)&sw1[k * 128 + f];
        h.x += a * w.x; h.y += a * w.y; h.z += a * w.z; h.w += a * w.w;
    }
    h.x = fmaxf(h.x, 0.f); h.y = fmaxf(h.y, 0.f);
    h.z = fmaxf(h.z, 0.f); h.w = fmaxf(h.w, 0.f);

    float o[16];
#pragma unroll
    for (int t = 0; t < 16; t++) o[t] = 0.0f;
    float hv[4] = {h.x, h.y, h.z, h.w};
#pragma unroll
    for (int j = 0; j < 4; j++) {
        const float* wrow = &sw2[(f + j) * 16];
        float hj = hv[j];
#pragma unroll
        for (int t = 0; t < 16; t++) o[t] += hj * wrow[t];
    }
#pragma unroll
    for (int off = 16; off > 0; off >>= 1)
#pragma unroll
        for (int t = 0; t < 16; t++) o[t] += __shfl_xor_sync(0xffffffffu, o[t], off);

    int f8 = lane * 8;
    float4 r0 = make_float4(0.f, 0.f, 0.f, 0.f);
    float4 r1 = make_float4(0.f, 0.f, 0.f, 0.f);
#pragma unroll
    for (int k = 0; k < 16; k++) {
        float hk = o[k] + sb2[k] + __shfl_sync(0xffffffffu, xv, k);
        const float4 wa = *(const float4*)&swp[k * 256 + f8];
        const float4 wb = *(const float4*)&swp[k * 256 + f8 + 4];
        r0.x += hk * wa.x; r0.y += hk * wa.y; r0.z += hk * wa.z; r0.w += hk * wa.w;
        r1.x += hk * wb.x; r1.y += hk * wb.y; r1.z += hk * wb.z; r1.w += hk * wb.w;
    }
    *(float4*)(PQ + (size_t)i * 256 + f8)     = r0;
    *(float4*)(PQ + (size_t)i * 256 + f8 + 4) = r1;
}

// ---------------- bf16x3 tensor-core GEMM, 8 warps ----------------
__device__ __forceinline__ void split4(float4 a, __nv_bfloat16* ph, __nv_bfloat16* pm) {
    __nv_bfloat162 h0 = __floats2bfloat162_rn(a.x, a.y);
    __nv_bfloat162 h1 = __floats2bfloat162_rn(a.z, a.w);
    __nv_bfloat162 m0 = __floats2bfloat162_rn(a.x - __bfloat162float(h0.x),
                                              a.y - __bfloat162float(h0.y));
    __nv_bfloat162 m1 = __floats2bfloat162_rn(a.z - __bfloat162float(h1.x),
                                              a.w - __bfloat162float(h1.y));
    *(__nv_bfloat162*)ph = h0; *(__nv_bfloat162*)(ph + 2) = h1;
    *(__nv_bfloat162*)pm = m0; *(__nv_bfloat162*)(pm + 2) = m1;
}

#define GEMM_SMEM 55296

__global__ __launch_bounds__(256)
void k_gemm_tc(const float* __restrict__ A, int lda,
               const float* __restrict__ B, long bStride,
               float* __restrict__ D, int ldd, long dStride,
               const float* __restrict__ bias, const float* __restrict__ rowscale,
               int M, int K, int N, int relu) {
    using namespace nvcuda;
    extern __shared__ char sm_raw[];
    __nv_bfloat16* Ah = (__nv_bfloat16*)sm_raw;
    __nv_bfloat16* Am = Ah + 2 * 2560;
    __nv_bfloat16* Bh = Am + 2 * 2560;
    __nv_bfloat16* Bm = Bh + 2 * 4352;

    B += (size_t)blockIdx.z * bStride;
    D += (size_t)blockIdx.z * dStride;

    int tid = threadIdx.x;
    int wid = tid >> 5, lane = tid & 31;
    int wm = wid >> 1, wn = wid & 1;
    int row0 = blockIdx.y * 64, col0 = blockIdx.x * 128;

    wmma::fragment<wmma::accumulator, 16, 16, 16, float> acc[4];
#pragma unroll
    for (int ni = 0; ni < 4; ni++) wmma::fill_fragment(acc[ni], 0.0f);

    int KT = (K + 31) >> 5;

    auto loadA = [&](int kt, int buf) {
        int k0 = kt << 5;
#pragma unroll
        for (int i = 0; i < 2; i++) {
            int v = tid + (i << 8);
            int r = v >> 3, c = (v & 7) << 2;
            int gr = row0 + r;
            float4 a = make_float4(0.f, 0.f, 0.f, 0.f);
            if (gr < M && k0 + c < K) a = *(const float4*)(A + (size_t)gr * lda + k0 + c);
            int idx = buf * 2560 + r * 40 + c;
            split4(a, &Ah[idx], &Am[idx]);
        }
    };
    auto loadB = [&](int kt, int buf) {
        int k0 = kt << 5;
#pragma unroll
        for (int i = 0; i < 4; i++) {
            int v = tid + (i << 8);
            int r = v >> 5, c = (v & 31) << 2;
            int gc = col0 + c;
            float4 b = make_float4(0.f, 0.f, 0.f, 0.f);
            if (gc < N && k0 + r < K) b = *(const float4*)(B + (size_t)(k0 + r) * N + gc);
            int idx = buf * 4352 + r * 136 + c;
            split4(b, &Bh[idx], &Bm[idx]);
        }
    };

    loadA(0, 0); loadB(0, 0);
    __syncthreads();
    for (int kt = 0; kt < KT; kt++) {
        int buf = kt & 1;
        if (kt + 1 < KT) { loadA(kt + 1, buf ^ 1); loadB(kt + 1, buf ^ 1); }
#pragma unroll
        for (int ks = 0; ks < 2; ks++) {
            wmma::fragment<wmma::matrix_a, 16, 16, 16, __nv_bfloat16, wmma::row_major> ah, am;
            wmma::fragment<wmma::matrix_b, 16, 16, 16, __nv_bfloat16, wmma::row_major> bh[4], bm[4];
            int aoff = buf * 2560 + (wm * 16) * 40 + ks * 16;
            wmma::load_matrix_sync(ah, &Ah[aoff], 40);
            wmma::load_matrix_sync(am, &Am[aoff], 40);
#pragma unroll
            for (int ni = 0; ni < 4; ni++) {
                int boff = buf * 4352 + (ks * 16) * 136 + wn * 64 + ni * 16;
                wmma::load_matrix_sync(bh[ni], &Bh[boff], 136);
                wmma::load_matrix_sync(bm[ni], &Bm[boff], 136);
            }
#pragma unroll
            for (int ni = 0; ni < 4; ni++) {
                wmma::mma_sync(acc[ni], am, bh[ni], acc[ni]);
                wmma::mma_sync(acc[ni], ah, bm[ni], acc[ni]);
                wmma::mma_sync(acc[ni], ah, bh[ni], acc[ni]);
            }
        }
        __syncthreads();
    }

    bool direct = (bias == nullptr) && (rowscale == nullptr) && (relu == 0);
    if (direct) {   // NN % 16 == 0: full tiles or fully out of range
        int m0 = row0 + wm * 16;
        if (m0 + 16 <= M) {
#pragma unroll
            for (int ni = 0; ni < 4; ni++) {
                int n0 = col0 + wn * 64 + ni * 16;
                if (n0 < N)
                    wmma::store_matrix_sync(D + (size_t)m0 * ldd + n0, acc[ni], ldd,
                                            wmma::mem_row_major);
            }
        }
        return;
    }

    float* epi = (float*)sm_raw + wid * 320;
#pragma unroll
    for (int ni = 0; ni < 4; ni++) {
        wmma::store_matrix_sync(epi, acc[ni], 20, wmma::mem_row_major);
        __syncwarp();
        int r = lane >> 1, cb = (lane & 1) * 8;
        int m = row0 + wm * 16 + r;
        int n0 = col0 + wn * 64 + ni * 16 + cb;
        if (m < M && n0 < N) {
            float rs = rowscale ? rowscale[m] : 1.0f;
            float4 v0 = *(float4*)&epi[r * 20 + cb];
            float4 v1 = *(float4*)&epi[r * 20 + cb + 4];
            if (bias) {
                float4 b0 = *(const float4*)(bias + n0);
                float4 b1 = *(const float4*)(bias + n0 + 4);
                v0.x += rs * b0.x; v0.y += rs * b0.y; v0.z += rs * b0.z; v0.w += rs * b0.w;
                v1.x += rs * b1.x; v1.y += rs * b1.y; v1.z += rs * b1.z; v1.w += rs * b1.w;
            }
            if (relu) {
                v0.x = fmaxf(v0.x, 0.f); v0.y = fmaxf(v0.y, 0.f);
                v0.z = fmaxf(v0.z, 0.f); v0.w = fmaxf(v0.w, 0.f);
                v1.x = fmaxf(v1.x, 0.f); v1.y = fmaxf(v1.y, 0.f);
                v1.z = fmaxf(v1.z, 0.f); v1.w = fmaxf(v1.w, 0.f);
            }
            *(float4*)(D + (size_t)m * ldd + n0)     = v0;
            *(float4*)(D + (size_t)m * ldd + n0 + 4) = v1;
        }
        __syncwarp();
    }
}

// ---------------- shared edge-accumulation body (1 warp/node, 4 feats/lane) ----------
// acc = sum_nb relu( PQ[i,0:128] + PQ[src,128:256] + ea[rid]@W1e + b1 )  [lane's 4 feats]
// Weights stay in SMEM (one float4 LDS per k, shared by all 4 interleaved messages)
// to keep registers low for occupancy while preserving 8-way FMA ILP.
__device__ __forceinline__ float4 edge_accum(const float* __restrict__ PQ,
                                             const float* __restrict__ EA,
                                             const float* __restrict__ sw,
                                             unsigned long long bb01, unsigned long long bb23,
                                             int i, int lane, int f) {
    float4 p = *(const float4*)(PQ + (size_t)i * 256 + f);
    float4 acc = make_float4(0.f, 0.f, 0.f, 0.f);
    int s = g_off[i], s1 = g_off[i + 1];
    int l16 = lane & 15;
    bool hi = lane >= 16;

    for (; s + 4 <= s1; s += 4) {
        int2 e0 = g_csr[s], e1 = g_csr[s + 1], e2 = g_csr[s + 2], e3 = g_csr[s + 3];
        float4 q0 = *(const float4*)(PQ + (size_t)e0.x * 256 + 128 + f);
        float4 q1 = *(const float4*)(PQ + (size_t)e1.x * 256 + 128 + f);
        float4 q2 = *(const float4*)(PQ + (size_t)e2.x * 256 + 128 + f);
        float4 q3 = *(const float4*)(PQ + (size_t)e3.x * 256 + 128 + f);
        // lanes 0-15 carry even edge's ea row, lanes 16-31 the odd edge's
        float ev01 = EA[(size_t)(hi ? e1.y : e0.y) * 16 + l16];
        float ev23 = EA[(size_t)(hi ? e3.y : e2.y) * 16 + l16];

        unsigned long long m0a = bb01, m0b = bb23;
        unsigned long long m1a = bb01, m1b = bb23;
        unsigned long long m2a = bb01, m2b = bb23;
        unsigned long long m3a = bb01, m3b = bb23;
#pragma unroll
        for (int k = 0; k < 16; k++) {
            const float4 wv = *(const float4*)&sw[k * 128 + f];   // shared across 4 messages
            unsigned long long w01 = packf2(wv.x, wv.y);
            unsigned long long w23 = packf2(wv.z, wv.w);
            float v0 = __shfl_sync(0xffffffffu, ev01, k);
            float v1 = __shfl_sync(0xffffffffu, ev01, 16 + k);
            float v2 = __shfl_sync(0xffffffffu, ev23, k);
            float v3 = __shfl_sync(0xffffffffu, ev23, 16 + k);
            unsigned long long a0 = packf2(v0, v0);
            unsigned long long a1 = packf2(v1, v1);
            unsigned long long a2 = packf2(v2, v2);
            unsigned long long a3 = packf2(v3, v3);
            m0a = fmaf2(a0, w01, m0a); m0b = fmaf2(a0, w23, m0b);
            m1a = fmaf2(a1, w01, m1a); m1b = fmaf2(a1, w23, m1b);
            m2a = fmaf2(a2, w01, m2a); m2b = fmaf2(a2, w23, m2b);
            m3a = fmaf2(a3, w01, m3a); m3b = fmaf2(a3, w23, m3b);
        }
        float2 rA, rB;
        rA = unpackf2(m0a); rB = unpackf2(m0b);
        acc.x += fmaxf(p.x + q0.x + rA.x, 0.f);
        acc.y += fmaxf(p.y + q0.y + rA.y, 0.f);
        acc.z += fmaxf(p.z + q0.z + rB.x, 0.f);
        acc.w += fmaxf(p.w + q0.w + rB.y, 0.f);
        rA = unpackf2(m1a); rB = unpackf2(m1b);
        acc.x += fmaxf(p.x + q1.x + rA.x, 0.f);
        acc.y += fmaxf(p.y + q1.y + rA.y, 0.f);
        acc.z += fmaxf(p.z + q1.z + rB.x, 0.f);
        acc.w += fmaxf(p.w + q1.w + rB.y, 0.f);
        rA = unpackf2(m2a); rB = unpackf2(m2b);
        acc.x += fmaxf(p.x + q2.x + rA.x, 0.f);
        acc.y += fmaxf(p.y + q2.y + rA.y, 0.f);
        acc.z += fmaxf(p.z + q2.z + rB.x, 0.f);
        acc.w += fmaxf(p.w + q2.w + rB.y, 0.f);
        rA = unpackf2(m3a); rB = unpackf2(m3b);
        acc.x += fmaxf(p.x + q3.x + rA.x, 0.f);
        acc.y += fmaxf(p.y + q3.y + rA.y, 0.f);
        acc.z += fmaxf(p.z + q3.z + rB.x, 0.f);
        acc.w += fmaxf(p.w + q3.w + rB.y, 0.f);
    }
    for (; s < s1; s++) {
        int2 e = g_csr[s];
        float ev = (lane < 16) ? EA[(size_t)e.y * 16 + lane] : 0.0f;
        float4 q = *(const float4*)(PQ + (size_t)e.x * 256 + 128 + f);
        unsigned long long r01 = bb01, r23 = bb23;
#pragma unroll
        for (int k = 0; k < 16; k++) {
            const float4 wv = *(const float4*)&sw[k * 128 + f];
            float a = __shfl_sync(0xffffffffu, ev, k);
            unsigned long long aa = packf2(a, a);
            r01 = fmaf2(aa, packf2(wv.x, wv.y), r01);
            r23 = fmaf2(aa, packf2(wv.z, wv.w), r23);
        }
        float2 rA = unpackf2(r01), rB = unpackf2(r23);
        acc.x += fmaxf(p.x + q.x + rA.x, 0.f);
        acc.y += fmaxf(p.y + q.y + rA.y, 0.f);
        acc.z += fmaxf(p.z + q.z + rB.x, 0.f);
        acc.w += fmaxf(p.w + q.w + rB.y, 0.f);
    }
    return acc;
}

// ---------------- EA edge pass -> C ----------------
__global__ __launch_bounds__(256, 3)
void k_edge_f(const float* __restrict__ PQ,
              const float* __restrict__ EA, const float* __restrict__ W1e,
              const float* __restrict__ b1, float* __restrict__ S) {
    __shared__ float sw[16 * 128];
    __shared__ float sb[128];
    for (int v = threadIdx.x; v < 2048; v += blockDim.x) sw[v] = W1e[v];
    for (int v = threadIdx.x; v < 128; v += blockDim.x) sb[v] = b1[v];
    __syncthreads();
    int lane = threadIdx.x & 31;
    int f = lane * 4;
    float4 bbv = *(const float4*)&sb[f];
    unsigned long long bb01 = packf2(bbv.x, bbv.y);
    unsigned long long bb23 = packf2(bbv.z, bbv.w);

    int i = (blockIdx.x * blockDim.x + threadIdx.x) >> 5;
    if (i >= NN) return;
    float4 acc = edge_accum(PQ, EA, sw, bb01, bb23, i, lane, f);
    *(float4*)(S + (size_t)i * HD + f) = acc;
}

// ---------------- final EA edge pass fused with out = C@W2 + deg*b2 (N=16) ----------
__global__ __launch_bounds__(256, 3)
void k_edge_out(const float* __restrict__ PQ,
                const float* __restrict__ EA, const float* __restrict__ W1e,
                const float* __restrict__ b1, const float* __restrict__ W2,
                const float* __restrict__ b2, float* __restrict__ out) {
    __shared__ float sw[16 * 128];
    __shared__ float sb[128];
    __shared__ float sw2[128 * 16];
    __shared__ float sb2[16];
    for (int v = threadIdx.x; v < 2048; v += blockDim.x) { sw[v] = W1e[v]; sw2[v] = W2[v]; }
    for (int v = threadIdx.x; v < 128; v += blockDim.x) sb[v] = b1[v];
    if (threadIdx.x < 16) sb2[threadIdx.x] = b2[threadIdx.x];
    __syncthreads();
    int lane = threadIdx.x & 31;
    int f = lane * 4;
    float4 bbv = *(const float4*)&sb[f];
    unsigned long long bb01 = packf2(bbv.x, bbv.y);
    unsigned long long bb23 = packf2(bbv.z, bbv.w);

    int i = (blockIdx.x * blockDim.x + threadIdx.x) >> 5;
    if (i >= NN) return;
    float4 acc = edge_accum(PQ, EA, sw, bb01, bb23, i, lane, f);

    // out[i] = C[i]@W2 + deg[i]*b2, C row distributed 4 feats/lane
    float o[16];
#pragma unroll
    for (int t = 0; t < 16; t++) o[t] = 0.0f;
    float cv[4] = {acc.x, acc.y, acc.z, acc.w};
#pragma unroll
    for (int j = 0; j < 4; j++) {
        const float* wr = &sw2[(f + j) * 16];
        float cj = cv[j];
#pragma unroll
        for (int t = 0; t < 16; t++) o[t] += cj * wr[t];
    }
#pragma unroll
    for (int off = 16; off > 0; off >>= 1)
#pragma unroll
        for (int t = 0; t < 16; t++) o[t] += __shfl_xor_sync(0xffffffffu, o[t], off);
    if (lane < 16)
        out[(size_t)i * 16 + lane] = o[lane] + g_degf[i] * sb2[lane];
}

// ---------------- TAG propagation (norm folded via dis), ld = 512, 4x batched ---------
__global__ __launch_bounds__(256)
void k_prop(const float* __restrict__ Xc, float* __restrict__ Xn) {
    int i = (blockIdx.x * blockDim.x + threadIdx.x) >> 5;
    if (i >= NN) return;
    int lane = threadIdx.x & 31;
    int f = lane * 4;
    float4 acc = make_float4(0.f, 0.f, 0.f, 0.f);
    int s = g_off[i], s1 = g_off[i + 1];

    for (; s + 4 <= s1; s += 4) {
        int src[4];
#pragma unroll
        for (int j = 0; j < 4; j++) src[j] = g_csr[s + j].x;
        float nm[4]; float4 h[4];
#pragma unroll
        for (int j = 0; j < 4; j++) {
            nm[j] = __ldg(&g_dis[src[j]]);
            h[j] = *(const float4*)(Xc + (size_t)src[j] * 512 + f);
        }
#pragma unroll
        for (int j = 0; j < 4; j++) {
            acc.x += nm[j] * h[j].x; acc.y += nm[j] * h[j].y;
            acc.z += nm[j] * h[j].z; acc.w += nm[j] * h[j].w;
        }
    }
    for (; s < s1; s++) {
        int src = g_csr[s].x;
        float nm = __ldg(&g_dis[src]);
        float4 h = *(const float4*)(Xc + (size_t)src * 512 + f);
        acc.x += nm * h.x; acc.y += nm * h.y;
        acc.z += nm * h.z; acc.w += nm * h.w;
    }
    float di = __ldg(&g_dis[i]);
    acc.x *= di; acc.y *= di; acc.z *= di; acc.w *= di;
    *(float4*)(Xn + (size_t)i * 512 + f) = acc;
}

// ---------------- host ----------------
static void gemm(const float* A, int lda, const float* B, long bStride,
                 float* D, int ldd, long dStride,
                 const float* bias, const float* rowscale,
                 int M, int K, int N, int relu, int batch) {
    dim3 grid((N + 127) / 128, (M + 63) / 64, batch);
    k_gemm_tc<<<grid, 256, GEMM_SMEM>>>(A, lda, B, bStride, D, ldd, dStride,
                                        bias, rowscale, M, K, N, relu);
}

extern "C" void kernel_launch(void* const* d_in, const int* in_sizes, int n_in,
                              void* d_out, int out_size) {
    const float* x         = (const float*)d_in[0];
    const float* mask      = (const float*)d_in[1];
    const float* edge_attr = (const float*)d_in[2];
    const int* edge_index;
    int base;
    if (in_sizes[3] == 2 * EE) {
        edge_index = (const int*)d_in[3];
        base = 4;
    } else {
        edge_index = (const int*)d_in[n_in - 1];
        base = 3;
    }
    const float* m_w1   = (const float*)d_in[base + 0];
    const float* m_b1   = (const float*)d_in[base + 1];
    const float* m_w2   = (const float*)d_in[base + 2];
    const float* m_b2   = (const float*)d_in[base + 3];
    const float* ea0_w1 = (const float*)d_in[base + 4];
    const float* ea0_b1 = (const float*)d_in[base + 5];
    const float* ea0_w2 = (const float*)d_in[base + 6];
    const float* ea0_b2 = (const float*)d_in[base + 7];
    const float* tag0_w = (const float*)d_in[base + 8];
    const float* tag0_b = (const float*)d_in[base + 9];
    const float* ea1_w1 = (const float*)d_in[base + 10];
    const float* ea1_b1 = (const float*)d_in[base + 11];
    const float* ea1_w2 = (const float*)d_in[base + 12];
    const float* ea1_b2 = (const float*)d_in[base + 13];
    const float* tag1_w = (const float*)d_in[base + 14];
    const float* tag1_b = (const float*)d_in[base + 15];
    const float* ea2_w1 = (const float*)d_in[base + 16];
    const float* ea2_b1 = (const float*)d_in[base + 17];
    const float* ea2_w2 = (const float*)d_in[base + 18];
    const float* ea2_b2 = (const float*)d_in[base + 19];

    float *pPQ, *pC, *pH, *pX, *pdegf;
    cudaGetSymbolAddress((void**)&pPQ, g_PQ);
    cudaGetSymbolAddress((void**)&pC, g_C);
    cudaGetSymbolAddress((void**)&pH, g_H);
    cudaGetSymbolAddress((void**)&pX, g_X);
    cudaGetSymbolAddress((void**)&pdegf, g_degf);

    static int smem_set = 0;
    if (!smem_set) {
        cudaFuncSetAttribute(k_gemm_tc, cudaFuncAttributeMaxDynamicSharedMemorySize, GEMM_SMEM);
        smem_set = 1;
    }

    const int EB = 2500;    // node-warp kernels: 20000 warps / 8 per block

    // preprocessing: g_deg is zero on entry (invariant restored by k_scan)
    k_hist<<<(EE + 255) / 256, 256>>>(edge_index);
    k_scan<<<1, 1024>>>();
    k_fillmask<<<FILL_BLOCKS + MASK_BLOCKS, 256>>>(edge_index, mask, x,
                m_w1, m_b1, m_w2, m_b2, ea0_w1, pPQ);

    // ---- EA0 ----
    k_edge_f<<<EB, 256>>>(pPQ, edge_attr, ea0_w1 + 32 * 128, ea0_b1, pC);  // slot 3 <- ncu
    gemm(pC, 128, ea0_w2, 0, pX, 512, 0, ea0_b2, pdegf, NN, 128, 128, 1, 1);

    // ---- TAG0 ----
    k_prop<<<EB, 256>>>(pX,       pX + 128);
    k_prop<<<EB, 256>>>(pX + 128, pX + 256);
    k_prop<<<EB, 256>>>(pX + 256, pX + 384);
    gemm(pX, 512, tag0_w, 0, pH, 128, 0, tag0_b, nullptr, NN, 512, 128, 1, 1);

    // ---- EA1 ----
    gemm(pH, 128, ea1_w1, 128 * 128, pPQ, 256, 128, nullptr, nullptr, NN, 128, 128, 0, 2);
    k_edge_f<<<EB, 256>>>(pPQ, edge_attr, ea1_w1 + 256 * 128, ea1_b1, pC);
    gemm(pC, 128, ea1_w2, 0, pX, 512, 0, ea1_b2, pdegf, NN, 128, 128, 1, 1);

    // ---- TAG1 ----
    k_prop<<<EB, 256>>>(pX,       pX + 128);
    k_prop<<<EB, 256>>>(pX + 128, pX + 256);
    k_prop<<<EB, 256>>>(pX + 256, pX + 384);
    gemm(pX, 512, tag1_w, 0, pH, 128, 0, tag1_b, nullptr, NN, 512, 128, 1, 1);

    // ---- EA2 (edge pass fused with output projection) ----
    gemm(pH, 128, ea2_w1, 128 * 128, pPQ, 256, 128, nullptr, nullptr, NN, 128, 128, 0, 2);
    k_edge_out<<<EB, 256>>>(pPQ, edge_attr, ea2_w1 + 256 * 128, ea2_b1,
                            ea2_w2, ea2_b2, (float*)d_out);
}